// round 2
// baseline (speedup 1.0000x reference)
#include <cuda_runtime.h>
#include <math.h>

// ---------------- problem constants ----------------
#define BB 128      // batch
#define LL 128      // sentence length
#define AA 8        // aspect length
#define EE 300      // glove dim
#define HH 512      // lstm hidden
#define G4 2048     // 4*H
#define NHD 6       // heads
#define KAA 64      // relation attn hidden
#define TWOH 1024   // 2*H
#define OUTD 1324   // E + 2H
#define MROWS 17408 // B*L + B*A

// ---------------- scratch (static device globals; no allocation) ----------------
__device__ float g_XG[(long long)MROWS * 4096];   // gate preactivations, fwd cols [0,2048) bwd [2048,4096)
__device__ float g_h[2][2][BB * HH];              // [dir][buf][b*H+hid]
__device__ float g_c[2][BB * HH];
__device__ float g_ah[2][2][BB * HH];             // aspect recurrence
__device__ float g_ac[2][BB * HH];
__device__ float g_af[BB * TWOH];                 // aspect feature (mean over A)
__device__ float g_Hcat[(long long)BB * LL * TWOH]; // sentence BiLSTM features
__device__ float g_Hrel[(long long)BB * LL * EE];   // adjacency-aggregated dep features
__device__ float g_score[BB * NHD * LL];

// ---------------- init ----------------
__global__ void k_init() {
    int i = blockIdx.x * blockDim.x + threadIdx.x;
    if (i < 2 * 2 * BB * HH) { ((float*)g_h)[i] = 0.f; ((float*)g_ah)[i] = 0.f; }
    if (i < 2 * BB * HH)     { ((float*)g_c)[i] = 0.f; ((float*)g_ac)[i] = 0.f; }
    if (i < BB * TWOH)       g_af[i] = 0.f;
}

// ---------------- input projection: gathered GEMM  XG[r,n] = glove[tok[r],:] . Wcat[n,:] + bcat[n]
// M=17408 (136 x 128), N=4096 (32 x 128), K=300 (pad to 304)
__global__ __launch_bounds__(256) void k_inputproj(
    const int* __restrict__ sentence, const int* __restrict__ aspect,
    const float* __restrict__ glove,
    const float* __restrict__ Wf, const float* __restrict__ Wb,
    const float* __restrict__ bf, const float* __restrict__ bb)
{
    __shared__ float As[8][128];
    __shared__ float Bs[8][128];
    __shared__ int   s_tok[128];
    int m0 = blockIdx.x * 128, n0 = blockIdx.y * 128;
    int tid = threadIdx.x;
    if (tid < 128) {
        int r = m0 + tid;
        s_tok[tid] = (r < BB * LL) ? sentence[r] : aspect[r - BB * LL];
    }
    __syncthreads();
    const float* W = (n0 < G4) ? Wf : Wb;
    int nb = (n0 < G4) ? n0 : n0 - G4;
    float acc[8][8];
#pragma unroll
    for (int i = 0; i < 8; i++)
#pragma unroll
        for (int j = 0; j < 8; j++) acc[i][j] = 0.f;
    int tm = tid >> 4, tn = tid & 15;
    int lm = tid >> 1, lk = (tid & 1) * 4;
    for (int k0 = 0; k0 < 300; k0 += 8) {
        const float* arow = glove + (long long)s_tok[lm] * 300;
        const float* wrow = W + (long long)(nb + lm) * 300;
#pragma unroll
        for (int j = 0; j < 4; j++) {
            int k = k0 + lk + j;
            As[lk + j][lm] = (k < 300) ? arow[k] : 0.f;
            Bs[lk + j][lm] = (k < 300) ? wrow[k] : 0.f;
        }
        __syncthreads();
#pragma unroll
        for (int kk = 0; kk < 8; kk++) {
            float a[8], w[8];
#pragma unroll
            for (int i = 0; i < 8; i++) a[i] = As[kk][tm * 8 + i];
#pragma unroll
            for (int j = 0; j < 8; j++) w[j] = Bs[kk][tn * 8 + j];
#pragma unroll
            for (int i = 0; i < 8; i++)
#pragma unroll
                for (int j = 0; j < 8; j++) acc[i][j] += a[i] * w[j];
        }
        __syncthreads();
    }
    const float* bias = (n0 < G4) ? bf : bb;
#pragma unroll
    for (int i = 0; i < 8; i++) {
        long long r = m0 + tm * 8 + i;
        float* orow = g_XG + r * 4096 + n0;
#pragma unroll
        for (int j = 0; j < 8; j++)
            orow[tn * 8 + j] = acc[i][j] + bias[nb + tn * 8 + j];
    }
}

// ---------------- one LSTM step (both directions via blockIdx.y), per-block hidden slice of 8
// grid (64, 2), 256 threads (2 warps/SMSP for issue-rate). C tile: 128 batch x 32 gate-cols, K = 512.
__device__ __forceinline__ float sigf(float x) { return 1.f / (1.f + expf(-x)); }

__global__ __launch_bounds__(256) void k_lstm_step(
    const float* __restrict__ Whf, const float* __restrict__ Whb,
    int t, int is_aspect)
{
    int dir = blockIdx.y;
    int ct  = blockIdx.x;                 // hidden slice [ct*8, ct*8+8)
    const float* W = dir ? Whb : Whf;
    int nsteps = is_aspect ? AA : LL;
    int tt = dir ? (nsteps - 1 - t) : t;
    float* hbufs = is_aspect ? &g_ah[0][0][0] : &g_h[0][0][0];
    float* cbase = is_aspect ? &g_ac[0][0]    : &g_c[0][0];
    const float* hin = hbufs + (dir * 2 + (t & 1)) * (BB * HH);
    float*       hout = hbufs + (dir * 2 + ((t + 1) & 1)) * (BB * HH);
    float*       cptr = cbase + dir * (BB * HH);

    __shared__ float Hs[16][128];
    __shared__ float Ws[16][32];
    __shared__ float s_g[128][33];

    int tid = threadIdx.x;
    int tm = tid >> 3;    // 0..31, rows tm*4..
    int tn = tid & 7;     // cols tn*4..
    float acc[4][4];
#pragma unroll
    for (int i = 0; i < 4; i++)
#pragma unroll
        for (int j = 0; j < 4; j++) acc[i][j] = 0.f;

    int lm = tid >> 1;            // 0..127 (H row = batch)
    int lk = (tid & 1) * 8;       // 0 or 8
    int wcc = tid >> 2;           // 0..63 (only <32 used for W)
    int wkk = (tid & 3) * 4;      // 0,4,8,12
    int wgate = wcc >> 3, whid = wcc & 7;
    const float* wrowbase = W + (long long)(wgate * HH + ct * 8 + whid) * HH;

    for (int k0 = 0; k0 < HH; k0 += 16) {
        {
            const float* hrow = hin + lm * HH + k0 + lk;
            float4 v0 = *(const float4*)(hrow);
            float4 v1 = *(const float4*)(hrow + 4);
            Hs[lk + 0][lm] = v0.x; Hs[lk + 1][lm] = v0.y;
            Hs[lk + 2][lm] = v0.z; Hs[lk + 3][lm] = v0.w;
            Hs[lk + 4][lm] = v1.x; Hs[lk + 5][lm] = v1.y;
            Hs[lk + 6][lm] = v1.z; Hs[lk + 7][lm] = v1.w;
        }
        if (tid < 128) {
            float4 w = *(const float4*)(wrowbase + k0 + wkk);
            Ws[wkk + 0][wcc] = w.x; Ws[wkk + 1][wcc] = w.y;
            Ws[wkk + 2][wcc] = w.z; Ws[wkk + 3][wcc] = w.w;
        }
        __syncthreads();
#pragma unroll
        for (int kk = 0; kk < 16; kk++) {
            float a[4], w[4];
#pragma unroll
            for (int i = 0; i < 4; i++) a[i] = Hs[kk][tm * 4 + i];
#pragma unroll
            for (int j = 0; j < 4; j++) w[j] = Ws[kk][tn * 4 + j];
#pragma unroll
            for (int i = 0; i < 4; i++)
#pragma unroll
                for (int j = 0; j < 4; j++) acc[i][j] += a[i] * w[j];
        }
        __syncthreads();
    }

    // add xg preactivations, stage to smem so gates regroup per hidden unit
#pragma unroll
    for (int i = 0; i < 4; i++) {
        int b = tm * 4 + i;
        long long r = is_aspect ? (long long)(BB * LL + b * AA + tt)
                                : (long long)(b * LL + tt);
        const float* xrow = g_XG + r * 4096 + dir * G4;
#pragma unroll
        for (int j = 0; j < 4; j++) {
            int cc = tn * 4 + j;
            int gate = cc >> 3, hidl = cc & 7;
            s_g[b][cc] = acc[i][j] + xrow[gate * HH + ct * 8 + hidl];
        }
    }
    __syncthreads();

    // pointwise: 128 batch x 8 hidden = 1024 states / 256 threads
#pragma unroll
    for (int p = 0; p < 4; p++) {
        int idx = tid + p * 256;
        int b = idx & 127;
        int hidl = idx >> 7;
        float gi = s_g[b][hidl];
        float gf = s_g[b][8 + hidl];
        float gg = s_g[b][16 + hidl];
        float go = s_g[b][24 + hidl];
        int hid = ct * 8 + hidl;
        float c_old = cptr[b * HH + hid];
        float c_new = sigf(gf) * c_old + sigf(gi) * tanhf(gg);
        float h_new = sigf(go) * tanhf(c_new);
        cptr[b * HH + hid] = c_new;
        hout[b * HH + hid] = h_new;
        if (is_aspect) {
            g_af[b * TWOH + dir * HH + hid] += h_new * (1.f / AA);
        } else {
            g_Hcat[((long long)(b * LL + tt)) * TWOH + dir * HH + hid] = h_new;
        }
    }
}

// ---------------- Hrel: adjacency-aggregated dependency embeddings ----------------
__global__ __launch_bounds__(128) void k_hrel(
    const int* __restrict__ dep_tags, const int* __restrict__ dep_heads,
    const int* __restrict__ text_len, const float* __restrict__ dep_table)
{
    int bi = blockIdx.x;             // b*128 + i
    int b = bi >> 7, i = bi & 127;
    int tid = threadIdx.x;
    int tl = text_len[b];
    float* orow = g_Hrel + (long long)bi * EE;
    if (i >= tl) {
        for (int d = tid; d < EE; d += 128) orow[d] = 0.f;
        return;
    }
    __shared__ unsigned char s_adj[128];
    __shared__ int s_tag[128];
    int head_i = dep_heads[b * LL + i];
    {
        int j = tid;
        int hj = dep_heads[b * LL + j];
        bool a = (head_i == j) || (hj == i) || (j == i);
        s_adj[j] = (a && (j < tl)) ? 1 : 0;
        s_tag[j] = dep_tags[b * LL + j];
    }
    __syncthreads();
    float a0 = 0.f, a1 = 0.f, a2 = 0.f;
    for (int j = 0; j < 128; j++) {
        if (!s_adj[j]) continue;
        const float* er = dep_table + s_tag[j] * EE;
        a0 += er[tid];
        if (tid + 128 < EE) a1 += er[tid + 128];
        if (tid + 256 < EE) a2 += er[tid + 256];
    }
    orow[tid] = a0;
    if (tid + 128 < EE) orow[tid + 128] = a1;
    if (tid + 256 < EE) orow[tid + 256] = a2;
}

// ---------------- relation attention scores: per (row-tile, head) fused GEMM+relu+reduce
// grid (256, 6), 256 threads; C tile 64 rows x 64 KA, K=300
__global__ __launch_bounds__(256) void k_relscore(
    const float* __restrict__ W1, const float* __restrict__ b1,
    const float* __restrict__ W2, const float* __restrict__ b2)
{
    __shared__ float As[8][64];
    __shared__ float Bs[8][64];
    __shared__ float s_part[16][16][4];
    int m0 = blockIdx.x * 64;
    int h = blockIdx.y;
    int tid = threadIdx.x;
    int tm = tid >> 4, tn = tid & 15;
    const float* W1h = W1 + (long long)h * KAA * EE;
    float acc[4][4];
#pragma unroll
    for (int i = 0; i < 4; i++)
#pragma unroll
        for (int j = 0; j < 4; j++) acc[i][j] = 0.f;
    int lm = tid >> 2, lk = (tid & 3) * 2;
    for (int k0 = 0; k0 < 300; k0 += 8) {
        const float* ar = g_Hrel + (long long)(m0 + lm) * EE;
        const float* wr = W1h + (long long)lm * EE;
#pragma unroll
        for (int j = 0; j < 2; j++) {
            int k = k0 + lk + j;
            As[lk + j][lm] = (k < 300) ? ar[k] : 0.f;
            Bs[lk + j][lm] = (k < 300) ? wr[k] : 0.f;
        }
        __syncthreads();
#pragma unroll
        for (int kk = 0; kk < 8; kk++) {
            float a[4], w[4];
#pragma unroll
            for (int i = 0; i < 4; i++) a[i] = As[kk][tm * 4 + i];
#pragma unroll
            for (int j = 0; j < 4; j++) w[j] = Bs[kk][tn * 4 + j];
#pragma unroll
            for (int i = 0; i < 4; i++)
#pragma unroll
                for (int j = 0; j < 4; j++) acc[i][j] += a[i] * w[j];
        }
        __syncthreads();
    }
    float w2[4], bb1[4];
#pragma unroll
    for (int j = 0; j < 4; j++) {
        w2[j]  = W2[h * KAA + tn * 4 + j];
        bb1[j] = b1[h * KAA + tn * 4 + j];
    }
#pragma unroll
    for (int i = 0; i < 4; i++) {
        float s = 0.f;
#pragma unroll
        for (int j = 0; j < 4; j++) {
            float q = acc[i][j] + bb1[j];
            q = q > 0.f ? q : 0.f;
            s += q * w2[j];
        }
        s_part[tn][tm][i] = s;
    }
    __syncthreads();
    if (tid < 64) {
        int tm2 = tid >> 2, i = tid & 3;
        float s = 0.f;
#pragma unroll
        for (int t2 = 0; t2 < 16; t2++) s += s_part[t2][tm2][i];
        int r = m0 + tm2 * 4 + i;
        g_score[((r >> 7) * NHD + h) * LL + (r & 127)] = s + b2[h];
    }
}

// ---------------- relation softmax + dep_out ----------------
__global__ __launch_bounds__(128) void k_depout(const int* __restrict__ text_len,
                                                float* __restrict__ out)
{
    int b = blockIdx.x;
    int tid = threadIdx.x;
    int tl = text_len[b];
    __shared__ float s_attn[NHD][128];
    __shared__ float s_red[128];
    for (int h = 0; h < NHD; h++) {
        float v = (tid < tl) ? g_score[(b * NHD + h) * LL + tid] : -1e30f;
        s_red[tid] = v;
        __syncthreads();
        for (int o = 64; o > 0; o >>= 1) {
            if (tid < o) s_red[tid] = fmaxf(s_red[tid], s_red[tid + o]);
            __syncthreads();
        }
        float mx = s_red[0];
        __syncthreads();
        float e = (tid < tl) ? expf(v - mx) : 0.f;
        s_red[tid] = e;
        __syncthreads();
        for (int o = 64; o > 0; o >>= 1) {
            if (tid < o) s_red[tid] += s_red[tid + o];
            __syncthreads();
        }
        float inv = 1.f / s_red[0];
        __syncthreads();
        s_attn[h][tid] = e * inv;
    }
    __syncthreads();
    for (int d = tid; d < EE; d += 128) {
        float a0 = 0.f, a1 = 0.f, a2 = 0.f, a3 = 0.f, a4 = 0.f, a5 = 0.f;
        const float* hp = g_Hrel + (long long)b * LL * EE + d;
        for (int l = 0; l < LL; l++) {
            float v = hp[(long long)l * EE];
            a0 += s_attn[0][l] * v; a1 += s_attn[1][l] * v; a2 += s_attn[2][l] * v;
            a3 += s_attn[3][l] * v; a4 += s_attn[4][l] * v; a5 += s_attn[5][l] * v;
        }
        float r = fmaxf(a0, 0.f) + fmaxf(a1, 0.f) + fmaxf(a2, 0.f) +
                  fmaxf(a3, 0.f) + fmaxf(a4, 0.f) + fmaxf(a5, 0.f);
        out[b * OUTD + d] = r * (1.f / NHD);
    }
}

// ---------------- dot-product attention + gat_out ----------------
__global__ __launch_bounds__(256) void k_gatout(const int* __restrict__ text_len,
                                                float* __restrict__ out)
{
    int b = blockIdx.x;
    int tid = threadIdx.x;
    int tl = text_len[b];
    __shared__ float s_af[TWOH];
    __shared__ float s_dot[128];
    __shared__ float s_red[128];
    for (int d = tid; d < TWOH; d += 256) s_af[d] = g_af[b * TWOH + d];
    __syncthreads();
    int wid = tid >> 5, lane = tid & 31;
    for (int l = wid; l < LL; l += 8) {
        const float* fr = g_Hcat + ((long long)(b * LL + l)) * TWOH;
        float s = 0.f;
        for (int d = lane; d < TWOH; d += 32) s += fr[d] * s_af[d];
        for (int o = 16; o > 0; o >>= 1) s += __shfl_xor_sync(0xffffffffu, s, o);
        if (lane == 0) s_dot[l] = s;
    }
    __syncthreads();
    if (tid < 128) s_red[tid] = (tid < tl) ? s_dot[tid] : -1e30f;
    __syncthreads();
    for (int o = 64; o > 0; o >>= 1) {
        if (tid < o) s_red[tid] = fmaxf(s_red[tid], s_red[tid + o]);
        __syncthreads();
    }
    float mx = s_red[0];
    __syncthreads();
    if (tid < 128) {
        float e = (tid < tl) ? expf(s_dot[tid] - mx) : 0.f;
        s_dot[tid] = e;
        s_red[tid] = e;
    }
    __syncthreads();
    for (int o = 64; o > 0; o >>= 1) {
        if (tid < o) s_red[tid] += s_red[tid + o];
        __syncthreads();
    }
    float inv = 1.f / s_red[0];
    __syncthreads();
    if (tid < 128) s_dot[tid] *= inv;
    __syncthreads();
    for (int d = tid; d < TWOH; d += 256) {
        float a = 0.f;
        const float* fp = g_Hcat + (long long)b * LL * TWOH + d;
        for (int l = 0; l < LL; l++) a += s_dot[l] * fp[(long long)l * TWOH];
        out[b * OUTD + EE + d] = fmaxf(a, 0.f);
    }
}

// ---------------- launch ----------------
extern "C" void kernel_launch(void* const* d_in, const int* in_sizes, int n_in,
                              void* d_out, int out_size)
{
    (void)in_sizes; (void)n_in; (void)out_size;
    const int*   sentence  = (const int*)d_in[0];
    const int*   aspect    = (const int*)d_in[1];
    const int*   dep_tags  = (const int*)d_in[3];
    const int*   text_len  = (const int*)d_in[4];
    const int*   dep_heads = (const int*)d_in[7];
    const float* glove     = (const float*)d_in[10];
    const float* dep_table = (const float*)d_in[11];
    const float* W_ih_f    = (const float*)d_in[12];
    const float* W_hh_f    = (const float*)d_in[13];
    const float* b_f       = (const float*)d_in[14];
    const float* W_ih_b    = (const float*)d_in[15];
    const float* W_hh_b    = (const float*)d_in[16];
    const float* b_b       = (const float*)d_in[17];
    const float* att_W1    = (const float*)d_in[18];
    const float* att_b1    = (const float*)d_in[19];
    const float* att_W2    = (const float*)d_in[20];
    const float* att_b2    = (const float*)d_in[21];
    float* out = (float*)d_out;

    k_init<<<1024, 256>>>();
    k_inputproj<<<dim3(136, 32), 256>>>(sentence, aspect, glove,
                                        W_ih_f, W_ih_b, b_f, b_b);
    for (int t = 0; t < LL; t++)
        k_lstm_step<<<dim3(64, 2), 256>>>(W_hh_f, W_hh_b, t, 0);
    for (int t = 0; t < AA; t++)
        k_lstm_step<<<dim3(64, 2), 256>>>(W_hh_f, W_hh_b, t, 1);
    k_hrel<<<BB * LL, 128>>>(dep_tags, dep_heads, text_len, dep_table);
    k_relscore<<<dim3(256, NHD), 256>>>(att_W1, att_b1, att_W2, att_b2);
    k_depout<<<BB, 128>>>(text_len, out);
    k_gatout<<<BB, 256>>>(text_len, out);
}

// round 3
// speedup vs baseline: 1.2134x; 1.2134x over previous
#include <cuda_runtime.h>
#include <math.h>

// ---------------- problem constants ----------------
#define BB 128      // batch
#define LL 128      // sentence length
#define AA 8        // aspect length
#define EE 300      // glove dim
#define HH 512      // lstm hidden
#define G4 2048     // 4*H
#define NHD 6       // heads
#define KAA 64      // relation attn hidden
#define TWOH 1024   // 2*H
#define OUTD 1324   // E + 2H
#define MROWS 17408 // B*L + B*A

// ---------------- scratch (static device globals; no allocation) ----------------
__device__ float g_XG[(long long)MROWS * 4096];   // gate preactivations, fwd cols [0,2048) bwd [2048,4096)
__device__ float g_h[2][2][BB * HH];              // [dir][buf][b*H+hid]
__device__ float g_c[2][BB * HH];
__device__ float g_ah[2][2][BB * HH];             // aspect recurrence
__device__ float g_ac[2][BB * HH];
__device__ float g_af[BB * TWOH];                 // aspect feature (mean over A)
__device__ float g_Hcat[(long long)BB * LL * TWOH]; // sentence BiLSTM features
__device__ float g_Hrel[(long long)BB * LL * EE];   // adjacency-aggregated dep features
__device__ float g_score[BB * NHD * LL];

// ---------------- init ----------------
__global__ void k_init() {
    int i = blockIdx.x * blockDim.x + threadIdx.x;
    if (i < 2 * 2 * BB * HH) { ((float*)g_h)[i] = 0.f; ((float*)g_ah)[i] = 0.f; }
    if (i < 2 * BB * HH)     { ((float*)g_c)[i] = 0.f; ((float*)g_ac)[i] = 0.f; }
    if (i < BB * TWOH)       g_af[i] = 0.f;
}

// ---------------- tf32 mma helpers ----------------
__device__ __forceinline__ unsigned f2tf(float x) {
    unsigned r;
    asm("cvt.rna.tf32.f32 %0, %1;" : "=r"(r) : "f"(x));
    return r;
}
__device__ __forceinline__ void mma_tf32(float* d, unsigned a0, unsigned a1,
                                         unsigned a2, unsigned a3,
                                         unsigned b0, unsigned b1) {
    asm volatile(
        "mma.sync.aligned.m16n8k8.row.col.f32.tf32.tf32.f32 "
        "{%0,%1,%2,%3}, {%4,%5,%6,%7}, {%8,%9}, {%0,%1,%2,%3};"
        : "+f"(d[0]), "+f"(d[1]), "+f"(d[2]), "+f"(d[3])
        : "r"(a0), "r"(a1), "r"(a2), "r"(a3), "r"(b0), "r"(b1));
}

// ---------------- input projection: gathered GEMM  XG[r,n] = glove[tok[r],:] . Wcat[n,:] + bcat[n]
// M=17408 (136 x 128), N=4096 (32 x 128), K=300 (pad to 304)
__global__ __launch_bounds__(256) void k_inputproj(
    const int* __restrict__ sentence, const int* __restrict__ aspect,
    const float* __restrict__ glove,
    const float* __restrict__ Wf, const float* __restrict__ Wb,
    const float* __restrict__ bf, const float* __restrict__ bb)
{
    __shared__ float As[8][128];
    __shared__ float Bs[8][128];
    __shared__ int   s_tok[128];
    int m0 = blockIdx.x * 128, n0 = blockIdx.y * 128;
    int tid = threadIdx.x;
    if (tid < 128) {
        int r = m0 + tid;
        s_tok[tid] = (r < BB * LL) ? sentence[r] : aspect[r - BB * LL];
    }
    __syncthreads();
    const float* W = (n0 < G4) ? Wf : Wb;
    int nb = (n0 < G4) ? n0 : n0 - G4;
    float acc[8][8];
#pragma unroll
    for (int i = 0; i < 8; i++)
#pragma unroll
        for (int j = 0; j < 8; j++) acc[i][j] = 0.f;
    int tm = tid >> 4, tn = tid & 15;
    int lm = tid >> 1, lk = (tid & 1) * 4;
    for (int k0 = 0; k0 < 300; k0 += 8) {
        const float* arow = glove + (long long)s_tok[lm] * 300;
        const float* wrow = W + (long long)(nb + lm) * 300;
#pragma unroll
        for (int j = 0; j < 4; j++) {
            int k = k0 + lk + j;
            As[lk + j][lm] = (k < 300) ? arow[k] : 0.f;
            Bs[lk + j][lm] = (k < 300) ? wrow[k] : 0.f;
        }
        __syncthreads();
#pragma unroll
        for (int kk = 0; kk < 8; kk++) {
            float a[8], w[8];
#pragma unroll
            for (int i = 0; i < 8; i++) a[i] = As[kk][tm * 8 + i];
#pragma unroll
            for (int j = 0; j < 8; j++) w[j] = Bs[kk][tn * 8 + j];
#pragma unroll
            for (int i = 0; i < 8; i++)
#pragma unroll
                for (int j = 0; j < 8; j++) acc[i][j] += a[i] * w[j];
        }
        __syncthreads();
    }
    const float* bias = (n0 < G4) ? bf : bb;
#pragma unroll
    for (int i = 0; i < 8; i++) {
        long long r = m0 + tm * 8 + i;
        float* orow = g_XG + r * 4096 + n0;
#pragma unroll
        for (int j = 0; j < 8; j++)
            orow[tn * 8 + j] = acc[i][j] + bias[nb + tn * 8 + j];
    }
}

// ---------------- one LSTM step via tf32 tensor-core mma ----------------
// grid (64, 2), 256 threads = 8 warps. C tile: 128 batch x 32 gate-cols, K=512.
// Block col c (0..31) maps to global gate col (c>>3)*HH + ct*8 + (c&7).
// Smem strides of 68 words give lane bank = 4g+c (conflict-free fragment loads).
__device__ __forceinline__ float sigf(float x) { return 1.f / (1.f + expf(-x)); }

#define KC 64
#define HS_STRIDE 68

__global__ __launch_bounds__(256) void k_lstm_step(
    const float* __restrict__ Whf, const float* __restrict__ Whb,
    int t, int is_aspect)
{
    int dir = blockIdx.y;
    int ct  = blockIdx.x;                 // hidden slice [ct*8, ct*8+8)
    const float* W = dir ? Whb : Whf;
    int nsteps = is_aspect ? AA : LL;
    int tt = dir ? (nsteps - 1 - t) : t;
    float* hbufs = is_aspect ? &g_ah[0][0][0] : &g_h[0][0][0];
    float* cbase = is_aspect ? &g_ac[0][0]    : &g_c[0][0];
    const float* hin = hbufs + (dir * 2 + (t & 1)) * (BB * HH);
    float*       hout = hbufs + (dir * 2 + ((t + 1) & 1)) * (BB * HH);
    float*       cptr = cbase + dir * (BB * HH);

    __shared__ union {
        struct {
            unsigned Hs[128 * HS_STRIDE];   // 34816 B
            unsigned Ws[32 * HS_STRIDE];    // 8704 B
        } ld;
        float sg[128 * 33];                 // 16896 B
    } sm;

    int tid  = threadIdx.x;
    int wid  = tid >> 5;
    int lane = tid & 31;
    int g    = lane >> 2;      // 0..7
    int c    = lane & 3;       // 0..3
    int m0   = wid * 16;       // warp's 16-row strip

    float d[4][4];
#pragma unroll
    for (int nt = 0; nt < 4; nt++)
#pragma unroll
        for (int q = 0; q < 4; q++) d[nt][q] = 0.f;

    // W row mapping for loads: smem W row r (0..31) -> gmem row (r>>3)*HH + ct*8 + (r&7)
    int wr0 = (tid >> 3);                    // used below per-load
    (void)wr0;

    for (int k0 = 0; k0 < HH; k0 += KC) {
        // load H chunk: 128 rows x 64 cols; 256 threads x 8 float4
#pragma unroll
        for (int it = 0; it < 8; it++) {
            int row  = (tid >> 4) + it * 16;
            int col4 = (tid & 15) * 4;
            float4 v = *(const float4*)(hin + row * HH + k0 + col4);
            unsigned u0 = f2tf(v.x), u1 = f2tf(v.y), u2 = f2tf(v.z), u3 = f2tf(v.w);
            *(uint4*)(&sm.ld.Hs[row * HS_STRIDE + col4]) = make_uint4(u0, u1, u2, u3);
        }
        // load W chunk: 32 rows x 64 cols; 256 threads x 2 float4
#pragma unroll
        for (int e = 0; e < 2; e++) {
            int f4  = tid * 2 + e;
            int row = f4 >> 4;                  // 0..31
            int c4  = (f4 & 15) * 4;
            int wgate = row >> 3, whid = row & 7;
            const float* src = W + (long long)(wgate * HH + ct * 8 + whid) * HH + k0 + c4;
            float4 v = *(const float4*)src;
            unsigned u0 = f2tf(v.x), u1 = f2tf(v.y), u2 = f2tf(v.z), u3 = f2tf(v.w);
            *(uint4*)(&sm.ld.Ws[row * HS_STRIDE + c4]) = make_uint4(u0, u1, u2, u3);
        }
        __syncthreads();

        const unsigned* arow0 = &sm.ld.Hs[(m0 + g) * HS_STRIDE];
        const unsigned* arow1 = &sm.ld.Hs[(m0 + g + 8) * HS_STRIDE];
#pragma unroll
        for (int kk = 0; kk < KC / 8; kk++) {
            int kb = kk * 8;
            unsigned a0 = arow0[kb + c];
            unsigned a1 = arow1[kb + c];
            unsigned a2 = arow0[kb + c + 4];
            unsigned a3 = arow1[kb + c + 4];
#pragma unroll
            for (int nt = 0; nt < 4; nt++) {
                const unsigned* brow = &sm.ld.Ws[(nt * 8 + g) * HS_STRIDE];
                unsigned b0 = brow[kb + c];
                unsigned b1 = brow[kb + c + 4];
                mma_tf32(d[nt], a0, a1, a2, a3, b0, b1);
            }
        }
        __syncthreads();
    }

    // stage C fragments into s_g (aliases the load buffers; barrier above protects)
#pragma unroll
    for (int nt = 0; nt < 4; nt++)
#pragma unroll
        for (int q = 0; q < 4; q++) {
            int row = m0 + g + ((q >> 1) << 3);
            int col = nt * 8 + c * 2 + (q & 1);
            sm.sg[row * 33 + col] = d[nt][q];
        }
    __syncthreads();

    // pointwise: 128 batch x 8 hidden = 1024 states / 256 threads
#pragma unroll
    for (int p = 0; p < 4; p++) {
        int idx = tid + p * 256;
        int b = idx & 127;
        int hidl = idx >> 7;
        int hid = ct * 8 + hidl;
        long long r = is_aspect ? (long long)(BB * LL + b * AA + tt)
                                : (long long)(b * LL + tt);
        const float* xrow = g_XG + r * 4096 + dir * G4;
        float gi = sm.sg[b * 33 + hidl]      + xrow[0 * HH + hid];
        float gf = sm.sg[b * 33 + 8 + hidl]  + xrow[1 * HH + hid];
        float gg = sm.sg[b * 33 + 16 + hidl] + xrow[2 * HH + hid];
        float go = sm.sg[b * 33 + 24 + hidl] + xrow[3 * HH + hid];
        float c_old = cptr[b * HH + hid];
        float c_new = sigf(gf) * c_old + sigf(gi) * tanhf(gg);
        float h_new = sigf(go) * tanhf(c_new);
        cptr[b * HH + hid] = c_new;
        hout[b * HH + hid] = h_new;
        if (is_aspect) {
            g_af[b * TWOH + dir * HH + hid] += h_new * (1.f / AA);
        } else {
            g_Hcat[((long long)(b * LL + tt)) * TWOH + dir * HH + hid] = h_new;
        }
    }
}

// ---------------- Hrel: adjacency-aggregated dependency embeddings ----------------
__global__ __launch_bounds__(128) void k_hrel(
    const int* __restrict__ dep_tags, const int* __restrict__ dep_heads,
    const int* __restrict__ text_len, const float* __restrict__ dep_table)
{
    int bi = blockIdx.x;             // b*128 + i
    int b = bi >> 7, i = bi & 127;
    int tid = threadIdx.x;
    int tl = text_len[b];
    float* orow = g_Hrel + (long long)bi * EE;
    if (i >= tl) {
        for (int d = tid; d < EE; d += 128) orow[d] = 0.f;
        return;
    }
    __shared__ unsigned char s_adj[128];
    __shared__ int s_tag[128];
    int head_i = dep_heads[b * LL + i];
    {
        int j = tid;
        int hj = dep_heads[b * LL + j];
        bool a = (head_i == j) || (hj == i) || (j == i);
        s_adj[j] = (a && (j < tl)) ? 1 : 0;
        s_tag[j] = dep_tags[b * LL + j];
    }
    __syncthreads();
    float a0 = 0.f, a1 = 0.f, a2 = 0.f;
    for (int j = 0; j < 128; j++) {
        if (!s_adj[j]) continue;
        const float* er = dep_table + s_tag[j] * EE;
        a0 += er[tid];
        if (tid + 128 < EE) a1 += er[tid + 128];
        if (tid + 256 < EE) a2 += er[tid + 256];
    }
    orow[tid] = a0;
    if (tid + 128 < EE) orow[tid + 128] = a1;
    if (tid + 256 < EE) orow[tid + 256] = a2;
}

// ---------------- relation attention scores: per (row-tile, head) fused GEMM+relu+reduce
// grid (256, 6), 256 threads; C tile 64 rows x 64 KA, K=300
__global__ __launch_bounds__(256) void k_relscore(
    const float* __restrict__ W1, const float* __restrict__ b1,
    const float* __restrict__ W2, const float* __restrict__ b2)
{
    __shared__ float As[8][64];
    __shared__ float Bs[8][64];
    __shared__ float s_part[16][16][4];
    int m0 = blockIdx.x * 64;
    int h = blockIdx.y;
    int tid = threadIdx.x;
    int tm = tid >> 4, tn = tid & 15;
    const float* W1h = W1 + (long long)h * KAA * EE;
    float acc[4][4];
#pragma unroll
    for (int i = 0; i < 4; i++)
#pragma unroll
        for (int j = 0; j < 4; j++) acc[i][j] = 0.f;
    int lm = tid >> 2, lk = (tid & 3) * 2;
    for (int k0 = 0; k0 < 300; k0 += 8) {
        const float* ar = g_Hrel + (long long)(m0 + lm) * EE;
        const float* wr = W1h + (long long)lm * EE;
#pragma unroll
        for (int j = 0; j < 2; j++) {
            int k = k0 + lk + j;
            As[lk + j][lm] = (k < 300) ? ar[k] : 0.f;
            Bs[lk + j][lm] = (k < 300) ? wr[k] : 0.f;
        }
        __syncthreads();
#pragma unroll
        for (int kk = 0; kk < 8; kk++) {
            float a[4], w[4];
#pragma unroll
            for (int i = 0; i < 4; i++) a[i] = As[kk][tm * 4 + i];
#pragma unroll
            for (int j = 0; j < 4; j++) w[j] = Bs[kk][tn * 4 + j];
#pragma unroll
            for (int i = 0; i < 4; i++)
#pragma unroll
                for (int j = 0; j < 4; j++) acc[i][j] += a[i] * w[j];
        }
        __syncthreads();
    }
    float w2[4], bb1[4];
#pragma unroll
    for (int j = 0; j < 4; j++) {
        w2[j]  = W2[h * KAA + tn * 4 + j];
        bb1[j] = b1[h * KAA + tn * 4 + j];
    }
#pragma unroll
    for (int i = 0; i < 4; i++) {
        float s = 0.f;
#pragma unroll
        for (int j = 0; j < 4; j++) {
            float q = acc[i][j] + bb1[j];
            q = q > 0.f ? q : 0.f;
            s += q * w2[j];
        }
        s_part[tn][tm][i] = s;
    }
    __syncthreads();
    if (tid < 64) {
        int tm2 = tid >> 2, i = tid & 3;
        float s = 0.f;
#pragma unroll
        for (int t2 = 0; t2 < 16; t2++) s += s_part[t2][tm2][i];
        int r = m0 + tm2 * 4 + i;
        g_score[((r >> 7) * NHD + h) * LL + (r & 127)] = s + b2[h];
    }
}

// ---------------- relation softmax + dep_out ----------------
__global__ __launch_bounds__(128) void k_depout(const int* __restrict__ text_len,
                                                float* __restrict__ out)
{
    int b = blockIdx.x;
    int tid = threadIdx.x;
    int tl = text_len[b];
    __shared__ float s_attn[NHD][128];
    __shared__ float s_red[128];
    for (int h = 0; h < NHD; h++) {
        float v = (tid < tl) ? g_score[(b * NHD + h) * LL + tid] : -1e30f;
        s_red[tid] = v;
        __syncthreads();
        for (int o = 64; o > 0; o >>= 1) {
            if (tid < o) s_red[tid] = fmaxf(s_red[tid], s_red[tid + o]);
            __syncthreads();
        }
        float mx = s_red[0];
        __syncthreads();
        float e = (tid < tl) ? expf(v - mx) : 0.f;
        s_red[tid] = e;
        __syncthreads();
        for (int o = 64; o > 0; o >>= 1) {
            if (tid < o) s_red[tid] += s_red[tid + o];
            __syncthreads();
        }
        float inv = 1.f / s_red[0];
        __syncthreads();
        s_attn[h][tid] = e * inv;
    }
    __syncthreads();
    for (int d = tid; d < EE; d += 128) {
        float a0 = 0.f, a1 = 0.f, a2 = 0.f, a3 = 0.f, a4 = 0.f, a5 = 0.f;
        const float* hp = g_Hrel + (long long)b * LL * EE + d;
        for (int l = 0; l < LL; l++) {
            float v = hp[(long long)l * EE];
            a0 += s_attn[0][l] * v; a1 += s_attn[1][l] * v; a2 += s_attn[2][l] * v;
            a3 += s_attn[3][l] * v; a4 += s_attn[4][l] * v; a5 += s_attn[5][l] * v;
        }
        float r = fmaxf(a0, 0.f) + fmaxf(a1, 0.f) + fmaxf(a2, 0.f) +
                  fmaxf(a3, 0.f) + fmaxf(a4, 0.f) + fmaxf(a5, 0.f);
        out[b * OUTD + d] = r * (1.f / NHD);
    }
}

// ---------------- dot-product attention + gat_out ----------------
__global__ __launch_bounds__(256) void k_gatout(const int* __restrict__ text_len,
                                                float* __restrict__ out)
{
    int b = blockIdx.x;
    int tid = threadIdx.x;
    int tl = text_len[b];
    __shared__ float s_af[TWOH];
    __shared__ float s_dot[128];
    __shared__ float s_red[128];
    for (int d = tid; d < TWOH; d += 256) s_af[d] = g_af[b * TWOH + d];
    __syncthreads();
    int wid = tid >> 5, lane = tid & 31;
    for (int l = wid; l < LL; l += 8) {
        const float* fr = g_Hcat + ((long long)(b * LL + l)) * TWOH;
        float s = 0.f;
        for (int d = lane; d < TWOH; d += 32) s += fr[d] * s_af[d];
        for (int o = 16; o > 0; o >>= 1) s += __shfl_xor_sync(0xffffffffu, s, o);
        if (lane == 0) s_dot[l] = s;
    }
    __syncthreads();
    if (tid < 128) s_red[tid] = (tid < tl) ? s_dot[tid] : -1e30f;
    __syncthreads();
    for (int o = 64; o > 0; o >>= 1) {
        if (tid < o) s_red[tid] = fmaxf(s_red[tid], s_red[tid + o]);
        __syncthreads();
    }
    float mx = s_red[0];
    __syncthreads();
    if (tid < 128) {
        float e = (tid < tl) ? expf(s_dot[tid] - mx) : 0.f;
        s_dot[tid] = e;
        s_red[tid] = e;
    }
    __syncthreads();
    for (int o = 64; o > 0; o >>= 1) {
        if (tid < o) s_red[tid] += s_red[tid + o];
        __syncthreads();
    }
    float inv = 1.f / s_red[0];
    __syncthreads();
    if (tid < 128) s_dot[tid] *= inv;
    __syncthreads();
    for (int d = tid; d < TWOH; d += 256) {
        float a = 0.f;
        const float* fp = g_Hcat + (long long)b * LL * TWOH + d;
        for (int l = 0; l < LL; l++) a += s_dot[l] * fp[(long long)l * TWOH];
        out[b * OUTD + EE + d] = fmaxf(a, 0.f);
    }
}

// ---------------- launch ----------------
extern "C" void kernel_launch(void* const* d_in, const int* in_sizes, int n_in,
                              void* d_out, int out_size)
{
    (void)in_sizes; (void)n_in; (void)out_size;
    const int*   sentence  = (const int*)d_in[0];
    const int*   aspect    = (const int*)d_in[1];
    const int*   dep_tags  = (const int*)d_in[3];
    const int*   text_len  = (const int*)d_in[4];
    const int*   dep_heads = (const int*)d_in[7];
    const float* glove     = (const float*)d_in[10];
    const float* dep_table = (const float*)d_in[11];
    const float* W_ih_f    = (const float*)d_in[12];
    const float* W_hh_f    = (const float*)d_in[13];
    const float* b_f       = (const float*)d_in[14];
    const float* W_ih_b    = (const float*)d_in[15];
    const float* W_hh_b    = (const float*)d_in[16];
    const float* b_b       = (const float*)d_in[17];
    const float* att_W1    = (const float*)d_in[18];
    const float* att_b1    = (const float*)d_in[19];
    const float* att_W2    = (const float*)d_in[20];
    const float* att_b2    = (const float*)d_in[21];
    float* out = (float*)d_out;

    k_init<<<1024, 256>>>();
    k_inputproj<<<dim3(136, 32), 256>>>(sentence, aspect, glove,
                                        W_ih_f, W_ih_b, b_f, b_b);
    for (int t = 0; t < LL; t++)
        k_lstm_step<<<dim3(64, 2), 256>>>(W_hh_f, W_hh_b, t, 0);
    for (int t = 0; t < AA; t++)
        k_lstm_step<<<dim3(64, 2), 256>>>(W_hh_f, W_hh_b, t, 1);
    k_hrel<<<BB * LL, 128>>>(dep_tags, dep_heads, text_len, dep_table);
    k_relscore<<<dim3(256, NHD), 256>>>(att_W1, att_b1, att_W2, att_b2);
    k_depout<<<BB, 128>>>(text_len, out);
    k_gatout<<<BB, 256>>>(text_len, out);
}